// round 4
// baseline (speedup 1.0000x reference)
#include <cuda_runtime.h>
#include <cuda_bf16.h>
#include <math.h>
#include <stdint.h>

// ---------------------------------------------------------------------------
// Problem constants
// ---------------------------------------------------------------------------
#define BATCH   8
#define SEQ     1024
#define ROWS    (BATCH * SEQ)        // 8192
#define EMBED   768
#define HEADS   12
#define HDIM    64
#define QKDIM   (2 * EMBED)          // 1536
#define MLPDIM  3072
#define BH      (BATCH * HEADS)      // 96

// ---------------------------------------------------------------------------
// Device scratch (static globals — allocation-free)
// ---------------------------------------------------------------------------
__device__ float g_h1[(size_t)ROWS * EMBED];
__device__ float g_qk[(size_t)ROWS * QKDIM];
__device__ float g_v [(size_t)ROWS * EMBED];
__device__ float g_att[(size_t)ROWS * EMBED];
__device__ float g_x2[(size_t)ROWS * EMBED];
__device__ float g_h2[(size_t)ROWS * EMBED];
__device__ float g_m1[(size_t)ROWS * MLPDIM];

// ---------------------------------------------------------------------------
// Helpers
// ---------------------------------------------------------------------------
__device__ __forceinline__ void mma_tf32(float c[4],
                                         const uint32_t a[4],
                                         const uint32_t b[2]) {
    asm volatile(
        "mma.sync.aligned.m16n8k8.row.col.f32.tf32.tf32.f32 "
        "{%0,%1,%2,%3}, {%4,%5,%6,%7}, {%8,%9}, {%0,%1,%2,%3};"
        : "+f"(c[0]), "+f"(c[1]), "+f"(c[2]), "+f"(c[3])
        : "r"(a[0]), "r"(a[1]), "r"(a[2]), "r"(a[3]),
          "r"(b[0]), "r"(b[1]));
}

__device__ __forceinline__ void cp16(uint32_t dst, const void* src) {
    asm volatile("cp.async.cg.shared.global [%0], [%1], 16;" :: "r"(dst), "l"(src));
}
__device__ __forceinline__ void cp_commit() {
    asm volatile("cp.async.commit_group;");
}
__device__ __forceinline__ void cp_wait1() {
    asm volatile("cp.async.wait_group 1;");
}

__device__ __forceinline__ uint4 f4bits(float4 v) {
    uint4 u;
    u.x = __float_as_uint(v.x); u.y = __float_as_uint(v.y);
    u.z = __float_as_uint(v.z); u.w = __float_as_uint(v.w);
    return u;
}

// ---------------------------------------------------------------------------
// LayerNorm: one block per row
// ---------------------------------------------------------------------------
__global__ __launch_bounds__(256)
void ln_kernel(const float* __restrict__ x, const float* __restrict__ g,
               const float* __restrict__ b, float* __restrict__ out)
{
    __shared__ float s1[8], s2[8];
    const long row = blockIdx.x;
    const float* p = x + row * EMBED;
    const int tid = threadIdx.x;

    float v0 = p[tid], v1 = p[tid + 256], v2 = p[tid + 512];
    float s = v0 + v1 + v2;
    float q = v0 * v0 + v1 * v1 + v2 * v2;
    #pragma unroll
    for (int o = 16; o; o >>= 1) {
        s += __shfl_xor_sync(0xFFFFFFFFu, s, o);
        q += __shfl_xor_sync(0xFFFFFFFFu, q, o);
    }
    if ((tid & 31) == 0) { s1[tid >> 5] = s; s2[tid >> 5] = q; }
    __syncthreads();
    if (tid < 32) {
        s = (tid < 8) ? s1[tid] : 0.0f;
        q = (tid < 8) ? s2[tid] : 0.0f;
        #pragma unroll
        for (int o = 4; o; o >>= 1) {
            s += __shfl_xor_sync(0xFFFFFFFFu, s, o);
            q += __shfl_xor_sync(0xFFFFFFFFu, q, o);
        }
        if (tid == 0) { s1[0] = s; s2[0] = q; }
    }
    __syncthreads();
    const float inv = 1.0f / (float)EMBED;
    const float mu  = s1[0] * inv;
    const float var = s2[0] * inv - mu * mu;
    const float rstd = rsqrtf(var + 1e-5f);
    float* po = out + row * EMBED;
    po[tid      ] = (v0 - mu) * rstd * g[tid      ] + b[tid      ];
    po[tid + 256] = (v1 - mu) * rstd * g[tid + 256] + b[tid + 256];
    po[tid + 512] = (v2 - mu) * rstd * g[tid + 512] + b[tid + 512];
}

// ---------------------------------------------------------------------------
// TF32 GEMM v2: cp.async double-buffered, raw fp32 operands (HW truncation).
// 128x128 tile, BK=32, 256 threads, warp tile 64x32 (4x4 m16n8k8).
// Smem layout (words): A stage s at s*4608, [128][36]; B stage s at
// 9216 + s*4352, [32][136]. Total 17920 words = 71680 B.
// ---------------------------------------------------------------------------
#define EPI_NONE     0
#define EPI_BIAS     1
#define EPI_GELU     2
#define EPI_BIASRES  3

#define GEMM_SMEM_BYTES 71680

template<int EPI>
__global__ __launch_bounds__(256)
void gemm_tf32(const float* __restrict__ A, const float* __restrict__ B,
               const float* __restrict__ bias, const float* __restrict__ res,
               float* __restrict__ C, int M, int N, int K)
{
    extern __shared__ uint32_t sg[];
    const uint32_t sbase = (uint32_t)__cvta_generic_to_shared(sg);

    const int tid  = threadIdx.x;
    const int bm   = blockIdx.y * 128;
    const int bn   = blockIdx.x * 128;
    const int w    = tid >> 5;
    const int lane = tid & 31;
    const int m0   = (w >> 2) * 64;
    const int n0   = (w & 3) * 32;
    const int g    = lane >> 2;
    const int tq   = lane & 3;

    // async loaders
    const int ar  = tid >> 1;          // A row 0..127
    const int ac  = (tid & 1) * 16;    // A k chunk base
    const int br  = tid >> 3;          // B k-row 0..31
    const int bc8 = (tid & 7) * 16;    // B col chunk base

    const float* Ag = A + (long)(bm + ar) * K + ac;
    const float* Bg = B + (long)br * N + bn + bc8;

    float acc[4][4][4];
    #pragma unroll
    for (int i = 0; i < 4; i++)
        #pragma unroll
        for (int j = 0; j < 4; j++)
            #pragma unroll
            for (int r = 0; r < 4; r++) acc[i][j][r] = 0.0f;

    auto issue = [&](int k0, int s) {
        const uint32_t ad = sbase + (s * 4608 + ar * 36 + ac) * 4;
        const float* ap = Ag + k0;
        #pragma unroll
        for (int i = 0; i < 4; i++) cp16(ad + i * 16, ap + i * 4);
        const uint32_t bd = sbase + (9216 + s * 4352 + br * 136 + bc8) * 4;
        const float* bp = Bg + (long)k0 * N;
        #pragma unroll
        for (int i = 0; i < 4; i++) cp16(bd + i * 16, bp + i * 4);
    };

    const int NT = K >> 5;
    issue(0, 0);
    cp_commit();

    for (int t = 0; t < NT; t++) {
        if (t + 1 < NT) issue((t + 1) << 5, (t + 1) & 1);
        cp_commit();
        cp_wait1();
        __syncthreads();

        const uint32_t* As = sg + (t & 1) * 4608;
        const uint32_t* Bs = sg + 9216 + (t & 1) * 4352;

        #pragma unroll
        for (int kk = 0; kk < 32; kk += 8) {
            uint32_t af[4][4];
            uint32_t bf[4][2];
            #pragma unroll
            for (int i = 0; i < 4; i++) {
                const uint32_t* ap = As + (m0 + i * 16 + g) * 36 + kk + tq;
                af[i][0] = ap[0];
                af[i][1] = ap[8 * 36];
                af[i][2] = ap[4];
                af[i][3] = ap[8 * 36 + 4];
            }
            #pragma unroll
            for (int j = 0; j < 4; j++) {
                bf[j][0] = Bs[(kk + tq    ) * 136 + n0 + j * 8 + g];
                bf[j][1] = Bs[(kk + tq + 4) * 136 + n0 + j * 8 + g];
            }
            #pragma unroll
            for (int i = 0; i < 4; i++)
                #pragma unroll
                for (int j = 0; j < 4; j++)
                    mma_tf32(acc[i][j], af[i], bf[j]);
        }
        __syncthreads();
    }

    // epilogue
    #pragma unroll
    for (int i = 0; i < 4; i++) {
        const int row0 = bm + m0 + i * 16 + g;
        #pragma unroll
        for (int j = 0; j < 4; j++) {
            const int col = bn + n0 + j * 8 + tq * 2;
            float b0 = 0.0f, b1 = 0.0f;
            if (EPI != EPI_NONE) { b0 = bias[col]; b1 = bias[col + 1]; }
            #pragma unroll
            for (int half = 0; half < 2; half++) {
                const long base = (long)(row0 + half * 8) * N + col;
                float c0 = acc[i][j][half * 2 + 0];
                float c1 = acc[i][j][half * 2 + 1];
                if (EPI != EPI_NONE) { c0 += b0; c1 += b1; }
                if (EPI == EPI_GELU) {
                    c0 = 0.5f * c0 * (1.0f + erff(c0 * 0.70710678118654752f));
                    c1 = 0.5f * c1 * (1.0f + erff(c1 * 0.70710678118654752f));
                }
                if (EPI == EPI_BIASRES) { c0 += res[base]; c1 += res[base + 1]; }
                float2 o; o.x = c0; o.y = c1;
                *(float2*)(C + base) = o;
            }
        }
    }
}

// ---------------------------------------------------------------------------
// Fused flash attention v2 (raw-fp32 tf32 mma, natural smem layouts,
// software-pipelined K/V loads).
// Grid: (SEQ/128, BH). Block 256 = 8 warps, warp w owns q rows [w*16, w*16+16).
// Smem (words): Qs [128][68] @0 (8704), Ks [64][68] @8704 (4352),
//               Vs [64][76] @13056 (4864), Ps 8x[16][68] @17920 (8704)
// total 26624 words = 106496 bytes.
// ---------------------------------------------------------------------------
#define FA_SMEM_BYTES 106496

__global__ __launch_bounds__(256, 2)
void flash_attn(const float* __restrict__ qk, const float* __restrict__ vbuf,
                float* __restrict__ out)
{
    extern __shared__ uint32_t sm[];
    uint32_t* Qs = sm;
    uint32_t* Ks = sm + 8704;
    uint32_t* Vs = sm + 13056;
    uint32_t* Ps = sm + 17920;

    const int bh = blockIdx.y;
    const int b  = bh / HEADS, h = bh % HEADS;
    const int q0 = blockIdx.x * 128;
    const int tid  = threadIdx.x;
    const int w    = tid >> 5;
    const int lane = tid & 31;
    const int g    = lane >> 2;
    const int tq   = lane & 3;
    uint32_t* Pw = Ps + w * (16 * 68);

    const float* Qg = qk + (long)b * SEQ * QKDIM + h * HDIM;
    const float* Kg = Qg + EMBED;
    const float* Vg = vbuf + (long)b * SEQ * EMBED + h * HDIM;

    // ---- load Q tile (128 x 64), scale 1/8, natural [m][k] stride 68 ----
    {
        const int qr = tid & 127;
        const int qc = (tid >> 7) * 32;
        const float* src = Qg + (long)(q0 + qr) * QKDIM + qc;
        #pragma unroll
        for (int i = 0; i < 32; i += 4) {
            float4 v = *(const float4*)(src + i);
            v.x *= 0.125f; v.y *= 0.125f; v.z *= 0.125f; v.w *= 0.125f;
            *(uint4*)&Qs[qr * 68 + qc + i] = f4bits(v);
        }
    }

    const int kr = tid & 63;
    const int kq = (tid >> 6) * 16;
    float4 kp[4], vp[4];

    // prefetch first K tile
    {
        const float* src = Kg + (long)kr * QKDIM + kq;
        #pragma unroll
        for (int i = 0; i < 4; i++) kp[i] = *(const float4*)(src + i * 4);
    }

    float oacc[8][4];
    #pragma unroll
    for (int j = 0; j < 8; j++)
        #pragma unroll
        for (int r = 0; r < 4; r++) oacc[j][r] = 0.0f;
    float mrow0 = -INFINITY, mrow1 = -INFINITY;
    float lrow0 = 0.0f, lrow1 = 0.0f;

    for (int kv = 0; kv < SEQ; kv += 64) {
        __syncthreads();   // prior reads of Ks/Vs/Ps complete (covers Q on iter 0)

        // ---- store K (raw bits) ----
        #pragma unroll
        for (int i = 0; i < 4; i++)
            *(uint4*)&Ks[kr * 68 + kq + i * 4] = f4bits(kp[i]);
        __syncthreads();   // Ks ready

        // ---- issue V load for this tile (hidden under S-mma + softmax) ----
        {
            const float* src = Vg + (long)(kv + kr) * EMBED + kq;
            #pragma unroll
            for (int i = 0; i < 4; i++) vp[i] = *(const float4*)(src + i * 4);
        }

        // ---- S = (Q/8) @ K^T ----
        float sacc[8][4];
        #pragma unroll
        for (int j = 0; j < 8; j++)
            #pragma unroll
            for (int r = 0; r < 4; r++) sacc[j][r] = 0.0f;

        const int mb = w * 16;
        #pragma unroll
        for (int kk = 0; kk < 64; kk += 8) {
            uint32_t af[4];
            const uint32_t* qp = Qs + (mb + g) * 68 + kk + tq;
            af[0] = qp[0];
            af[1] = qp[8 * 68];
            af[2] = qp[4];
            af[3] = qp[8 * 68 + 4];
            #pragma unroll
            for (int j = 0; j < 8; j++) {
                uint32_t bf[2];
                bf[0] = Ks[(j * 8 + g) * 68 + kk + tq    ];
                bf[1] = Ks[(j * 8 + g) * 68 + kk + tq + 4];
                mma_tf32(sacc[j], af, bf);
            }
        }

        // ---- online softmax ----
        float tmax0 = -INFINITY, tmax1 = -INFINITY;
        #pragma unroll
        for (int j = 0; j < 8; j++) {
            tmax0 = fmaxf(tmax0, fmaxf(sacc[j][0], sacc[j][1]));
            tmax1 = fmaxf(tmax1, fmaxf(sacc[j][2], sacc[j][3]));
        }
        #pragma unroll
        for (int o = 1; o < 4; o <<= 1) {
            tmax0 = fmaxf(tmax0, __shfl_xor_sync(0xFFFFFFFFu, tmax0, o));
            tmax1 = fmaxf(tmax1, __shfl_xor_sync(0xFFFFFFFFu, tmax1, o));
        }
        const float mnew0 = fmaxf(mrow0, tmax0);
        const float mnew1 = fmaxf(mrow1, tmax1);
        const float alpha0 = __expf(mrow0 - mnew0);
        const float alpha1 = __expf(mrow1 - mnew1);
        mrow0 = mnew0; mrow1 = mnew1;

        float sum0 = 0.0f, sum1 = 0.0f;
        #pragma unroll
        for (int j = 0; j < 8; j++) {
            sacc[j][0] = __expf(sacc[j][0] - mnew0);
            sacc[j][1] = __expf(sacc[j][1] - mnew0);
            sacc[j][2] = __expf(sacc[j][2] - mnew1);
            sacc[j][3] = __expf(sacc[j][3] - mnew1);
            sum0 += sacc[j][0] + sacc[j][1];
            sum1 += sacc[j][2] + sacc[j][3];
        }
        #pragma unroll
        for (int o = 1; o < 4; o <<= 1) {
            sum0 += __shfl_xor_sync(0xFFFFFFFFu, sum0, o);
            sum1 += __shfl_xor_sync(0xFFFFFFFFu, sum1, o);
        }
        lrow0 = lrow0 * alpha0 + sum0;
        lrow1 = lrow1 * alpha1 + sum1;

        #pragma unroll
        for (int j = 0; j < 8; j++) {
            oacc[j][0] *= alpha0; oacc[j][1] *= alpha0;
            oacc[j][2] *= alpha1; oacc[j][3] *= alpha1;
        }

        // ---- stage P (raw bits) ----
        #pragma unroll
        for (int j = 0; j < 8; j++) {
            Pw[ g      * 68 + j * 8 + tq * 2    ] = __float_as_uint(sacc[j][0]);
            Pw[ g      * 68 + j * 8 + tq * 2 + 1] = __float_as_uint(sacc[j][1]);
            Pw[(g + 8) * 68 + j * 8 + tq * 2    ] = __float_as_uint(sacc[j][2]);
            Pw[(g + 8) * 68 + j * 8 + tq * 2 + 1] = __float_as_uint(sacc[j][3]);
        }

        // ---- store V ----
        #pragma unroll
        for (int i = 0; i < 4; i++)
            *(uint4*)&Vs[kr * 76 + kq + i * 4] = f4bits(vp[i]);
        __syncthreads();   // Vs + Ps ready

        // ---- prefetch next K (hidden under PV-mma) ----
        if (kv + 64 < SEQ) {
            const float* src = Kg + (long)(kv + 64 + kr) * QKDIM + kq;
            #pragma unroll
            for (int i = 0; i < 4; i++) kp[i] = *(const float4*)(src + i * 4);
        }

        // ---- O += P @ V ----
        #pragma unroll
        for (int kk = 0; kk < 64; kk += 8) {
            uint32_t af[4];
            af[0] = Pw[ g      * 68 + kk + tq    ];
            af[1] = Pw[(g + 8) * 68 + kk + tq    ];
            af[2] = Pw[ g      * 68 + kk + tq + 4];
            af[3] = Pw[(g + 8) * 68 + kk + tq + 4];
            #pragma unroll
            for (int j = 0; j < 8; j++) {
                uint32_t bf[2];
                bf[0] = Vs[(kk + tq    ) * 76 + j * 8 + g];
                bf[1] = Vs[(kk + tq + 4) * 76 + j * 8 + g];
                mma_tf32(oacc[j], af, bf);
            }
        }
    }

    // ---- epilogue ----
    const float inv0 = 1.0f / lrow0;
    const float inv1 = 1.0f / lrow1;
    const long row0 = (long)(b * SEQ + q0 + w * 16 + g);
    #pragma unroll
    for (int j = 0; j < 8; j++) {
        const int col = h * HDIM + j * 8 + tq * 2;
        float2 o0; o0.x = oacc[j][0] * inv0; o0.y = oacc[j][1] * inv0;
        float2 o1; o1.x = oacc[j][2] * inv1; o1.y = oacc[j][3] * inv1;
        *(float2*)(out + row0 * EMBED + col)       = o0;
        *(float2*)(out + (row0 + 8) * EMBED + col) = o1;
    }
}

// ---------------------------------------------------------------------------
// Launch
// ---------------------------------------------------------------------------
extern "C" void kernel_launch(void* const* d_in, const int* in_sizes, int n_in,
                              void* d_out, int out_size)
{
    const float* x      = (const float*)d_in[0];
    const float* ln1_g  = (const float*)d_in[1];
    const float* ln1_b  = (const float*)d_in[2];
    const float* qk_w   = (const float*)d_in[3];
    const float* v_w    = (const float*)d_in[4];
    const float* proj_w = (const float*)d_in[5];
    const float* proj_b = (const float*)d_in[6];
    const float* ln2_g  = (const float*)d_in[7];
    const float* ln2_b  = (const float*)d_in[8];
    const float* fc1_w  = (const float*)d_in[9];
    const float* fc1_b  = (const float*)d_in[10];
    const float* fc2_w  = (const float*)d_in[11];
    const float* fc2_b  = (const float*)d_in[12];
    float* out = (float*)d_out;

    float *h1, *qkb, *vb, *att, *x2, *h2, *m1;
    cudaGetSymbolAddress((void**)&h1,  g_h1);
    cudaGetSymbolAddress((void**)&qkb, g_qk);
    cudaGetSymbolAddress((void**)&vb,  g_v);
    cudaGetSymbolAddress((void**)&att, g_att);
    cudaGetSymbolAddress((void**)&x2,  g_x2);
    cudaGetSymbolAddress((void**)&h2,  g_h2);
    cudaGetSymbolAddress((void**)&m1,  g_m1);

    static bool attr_done = false;
    if (!attr_done) {
        cudaFuncSetAttribute(flash_attn,
                             cudaFuncAttributeMaxDynamicSharedMemorySize,
                             FA_SMEM_BYTES);
        cudaFuncSetAttribute(gemm_tf32<EPI_NONE>,
                             cudaFuncAttributeMaxDynamicSharedMemorySize,
                             GEMM_SMEM_BYTES);
        cudaFuncSetAttribute(gemm_tf32<EPI_GELU>,
                             cudaFuncAttributeMaxDynamicSharedMemorySize,
                             GEMM_SMEM_BYTES);
        cudaFuncSetAttribute(gemm_tf32<EPI_BIASRES>,
                             cudaFuncAttributeMaxDynamicSharedMemorySize,
                             GEMM_SMEM_BYTES);
        attr_done = true;
    }

    // --- attention branch ---
    ln_kernel<<<ROWS, 256>>>(x, ln1_g, ln1_b, h1);

    gemm_tf32<EPI_NONE><<<dim3(QKDIM / 128, ROWS / 128), 256, GEMM_SMEM_BYTES>>>(
        h1, qk_w, nullptr, nullptr, qkb, ROWS, QKDIM, EMBED);
    gemm_tf32<EPI_NONE><<<dim3(EMBED / 128, ROWS / 128), 256, GEMM_SMEM_BYTES>>>(
        h1, v_w, nullptr, nullptr, vb, ROWS, EMBED, EMBED);

    flash_attn<<<dim3(SEQ / 128, BH), 256, FA_SMEM_BYTES>>>(qkb, vb, att);

    gemm_tf32<EPI_BIASRES><<<dim3(EMBED / 128, ROWS / 128), 256, GEMM_SMEM_BYTES>>>(
        att, proj_w, proj_b, x, x2, ROWS, EMBED, EMBED);

    // --- MLP branch ---
    ln_kernel<<<ROWS, 256>>>(x2, ln2_g, ln2_b, h2);

    gemm_tf32<EPI_GELU><<<dim3(MLPDIM / 128, ROWS / 128), 256, GEMM_SMEM_BYTES>>>(
        h2, fc1_w, fc1_b, nullptr, m1, ROWS, MLPDIM, EMBED);

    gemm_tf32<EPI_BIASRES><<<dim3(EMBED / 128, ROWS / 128), 256, GEMM_SMEM_BYTES>>>(
        m1, fc2_w, fc2_b, x2, out, ROWS, EMBED, MLPDIM);
}

// round 5
// speedup vs baseline: 1.0339x; 1.0339x over previous
#include <cuda_runtime.h>
#include <cuda_bf16.h>
#include <math.h>
#include <stdint.h>

// ---------------------------------------------------------------------------
// Problem constants
// ---------------------------------------------------------------------------
#define BATCH   8
#define SEQ     1024
#define ROWS    (BATCH * SEQ)        // 8192
#define EMBED   768
#define HEADS   12
#define HDIM    64
#define QKDIM   (2 * EMBED)          // 1536
#define MLPDIM  3072
#define BH      (BATCH * HEADS)      // 96

// ---------------------------------------------------------------------------
// Device scratch (static globals — allocation-free)
// ---------------------------------------------------------------------------
__device__ float g_h1[(size_t)ROWS * EMBED];
__device__ float g_qk[(size_t)ROWS * QKDIM];
__device__ float g_v [(size_t)ROWS * EMBED];
__device__ float g_att[(size_t)ROWS * EMBED];
__device__ float g_x2[(size_t)ROWS * EMBED];
__device__ float g_h2[(size_t)ROWS * EMBED];
__device__ float g_m1[(size_t)ROWS * MLPDIM];

// ---------------------------------------------------------------------------
// Helpers
// ---------------------------------------------------------------------------
__device__ __forceinline__ void mma_tf32(float c[4],
                                         const uint32_t a[4],
                                         const uint32_t b[2]) {
    asm volatile(
        "mma.sync.aligned.m16n8k8.row.col.f32.tf32.tf32.f32 "
        "{%0,%1,%2,%3}, {%4,%5,%6,%7}, {%8,%9}, {%0,%1,%2,%3};"
        : "+f"(c[0]), "+f"(c[1]), "+f"(c[2]), "+f"(c[3])
        : "r"(a[0]), "r"(a[1]), "r"(a[2]), "r"(a[3]),
          "r"(b[0]), "r"(b[1]));
}

__device__ __forceinline__ void cp16(uint32_t dst, const void* src) {
    asm volatile("cp.async.cg.shared.global [%0], [%1], 16;" :: "r"(dst), "l"(src));
}
__device__ __forceinline__ void cp_commit() {
    asm volatile("cp.async.commit_group;");
}
__device__ __forceinline__ void cp_wait2() {
    asm volatile("cp.async.wait_group 2;");
}
__device__ __forceinline__ void cp_wait0() {
    asm volatile("cp.async.wait_group 0;");
}

__device__ __forceinline__ uint4 f4bits(float4 v) {
    uint4 u;
    u.x = __float_as_uint(v.x); u.y = __float_as_uint(v.y);
    u.z = __float_as_uint(v.z); u.w = __float_as_uint(v.w);
    return u;
}

// ---------------------------------------------------------------------------
// LayerNorm: one block per row
// ---------------------------------------------------------------------------
__global__ __launch_bounds__(256)
void ln_kernel(const float* __restrict__ x, const float* __restrict__ g,
               const float* __restrict__ b, float* __restrict__ out)
{
    __shared__ float s1[8], s2[8];
    const long row = blockIdx.x;
    const float* p = x + row * EMBED;
    const int tid = threadIdx.x;

    float v0 = p[tid], v1 = p[tid + 256], v2 = p[tid + 512];
    float s = v0 + v1 + v2;
    float q = v0 * v0 + v1 * v1 + v2 * v2;
    #pragma unroll
    for (int o = 16; o; o >>= 1) {
        s += __shfl_xor_sync(0xFFFFFFFFu, s, o);
        q += __shfl_xor_sync(0xFFFFFFFFu, q, o);
    }
    if ((tid & 31) == 0) { s1[tid >> 5] = s; s2[tid >> 5] = q; }
    __syncthreads();
    if (tid < 32) {
        s = (tid < 8) ? s1[tid] : 0.0f;
        q = (tid < 8) ? s2[tid] : 0.0f;
        #pragma unroll
        for (int o = 4; o; o >>= 1) {
            s += __shfl_xor_sync(0xFFFFFFFFu, s, o);
            q += __shfl_xor_sync(0xFFFFFFFFu, q, o);
        }
        if (tid == 0) { s1[0] = s; s2[0] = q; }
    }
    __syncthreads();
    const float inv = 1.0f / (float)EMBED;
    const float mu  = s1[0] * inv;
    const float var = s2[0] * inv - mu * mu;
    const float rstd = rsqrtf(var + 1e-5f);
    float* po = out + row * EMBED;
    po[tid      ] = (v0 - mu) * rstd * g[tid      ] + b[tid      ];
    po[tid + 256] = (v1 - mu) * rstd * g[tid + 256] + b[tid + 256];
    po[tid + 512] = (v2 - mu) * rstd * g[tid + 512] + b[tid + 512];
}

// ---------------------------------------------------------------------------
// TF32 GEMM v3: 3-stage cp.async pipeline, raw fp32 operands (HW truncation).
// 128x128 tile, BK=32, 256 threads, warp tile 64x32 (4x4 m16n8k8).
// Smem (words): A stage s at s*4608 [128][36]; B stage s at 13824 + s*4352
// [32][136]. Total 26880 words = 107520 B.
// ---------------------------------------------------------------------------
#define EPI_NONE     0
#define EPI_BIAS     1
#define EPI_GELU     2
#define EPI_BIASRES  3

#define GEMM_SMEM_BYTES 107520

template<int EPI>
__global__ __launch_bounds__(256)
void gemm_tf32(const float* __restrict__ A, const float* __restrict__ B,
               const float* __restrict__ bias, const float* __restrict__ res,
               float* __restrict__ C, int M, int N, int K)
{
    extern __shared__ uint32_t sg[];
    const uint32_t sbase = (uint32_t)__cvta_generic_to_shared(sg);

    const int tid  = threadIdx.x;
    const int bm   = blockIdx.y * 128;
    const int bn   = blockIdx.x * 128;
    const int w    = tid >> 5;
    const int lane = tid & 31;
    const int m0   = (w >> 2) * 64;
    const int n0   = (w & 3) * 32;
    const int g    = lane >> 2;
    const int tq   = lane & 3;

    // async loaders
    const int ar  = tid >> 1;          // A row 0..127
    const int ac  = (tid & 1) * 16;    // A k chunk base
    const int br  = tid >> 3;          // B k-row 0..31
    const int bc8 = (tid & 7) * 16;    // B col chunk base

    const float* Ag = A + (long)(bm + ar) * K + ac;
    const float* Bg = B + (long)br * N + bn + bc8;

    float acc[4][4][4];
    #pragma unroll
    for (int i = 0; i < 4; i++)
        #pragma unroll
        for (int j = 0; j < 4; j++)
            #pragma unroll
            for (int r = 0; r < 4; r++) acc[i][j][r] = 0.0f;

    auto issue = [&](int k0, int s) {
        const uint32_t ad = sbase + (s * 4608 + ar * 36 + ac) * 4;
        const float* ap = Ag + k0;
        #pragma unroll
        for (int i = 0; i < 4; i++) cp16(ad + i * 16, ap + i * 4);
        const uint32_t bd = sbase + (13824 + s * 4352 + br * 136 + bc8) * 4;
        const float* bp = Bg + (long)k0 * N;
        #pragma unroll
        for (int i = 0; i < 4; i++) cp16(bd + i * 16, bp + i * 4);
    };

    const int NT = K >> 5;             // >= 24 for all our shapes
    issue(0, 0);  cp_commit();
    issue(32, 1); cp_commit();
    issue(64, 2); cp_commit();

    int st = 0;
    for (int t = 0; t < NT; t++) {
        cp_wait2();                    // stage st has landed
        __syncthreads();

        const uint32_t* As = sg + st * 4608;
        const uint32_t* Bs = sg + 13824 + st * 4352;

        #pragma unroll
        for (int kk = 0; kk < 32; kk += 8) {
            uint32_t af[4][4];
            uint32_t bf[4][2];
            #pragma unroll
            for (int i = 0; i < 4; i++) {
                const uint32_t* ap = As + (m0 + i * 16 + g) * 36 + kk + tq;
                af[i][0] = ap[0];
                af[i][1] = ap[8 * 36];
                af[i][2] = ap[4];
                af[i][3] = ap[8 * 36 + 4];
            }
            #pragma unroll
            for (int j = 0; j < 4; j++) {
                bf[j][0] = Bs[(kk + tq    ) * 136 + n0 + j * 8 + g];
                bf[j][1] = Bs[(kk + tq + 4) * 136 + n0 + j * 8 + g];
            }
            #pragma unroll
            for (int i = 0; i < 4; i++)
                #pragma unroll
                for (int j = 0; j < 4; j++)
                    mma_tf32(acc[i][j], af[i], bf[j]);
        }
        __syncthreads();               // stage st fully consumed

        if (t + 3 < NT) issue((t + 3) << 5, st);
        cp_commit();                   // unconditional: keeps group count exact
        st = (st == 2) ? 0 : st + 1;
    }

    // epilogue
    #pragma unroll
    for (int i = 0; i < 4; i++) {
        const int row0 = bm + m0 + i * 16 + g;
        #pragma unroll
        for (int j = 0; j < 4; j++) {
            const int col = bn + n0 + j * 8 + tq * 2;
            float b0 = 0.0f, b1 = 0.0f;
            if (EPI != EPI_NONE) { b0 = bias[col]; b1 = bias[col + 1]; }
            #pragma unroll
            for (int half = 0; half < 2; half++) {
                const long base = (long)(row0 + half * 8) * N + col;
                float c0 = acc[i][j][half * 2 + 0];
                float c1 = acc[i][j][half * 2 + 1];
                if (EPI != EPI_NONE) { c0 += b0; c1 += b1; }
                if (EPI == EPI_GELU) {
                    c0 = 0.5f * c0 * (1.0f + erff(c0 * 0.70710678118654752f));
                    c1 = 0.5f * c1 * (1.0f + erff(c1 * 0.70710678118654752f));
                }
                if (EPI == EPI_BIASRES) { c0 += res[base]; c1 += res[base + 1]; }
                float2 o; o.x = c0; o.y = c1;
                *(float2*)(C + base) = o;
            }
        }
    }
}

// ---------------------------------------------------------------------------
// Fused flash attention v3: cp.async K/V tile loads (no register prefetch,
// no cvt), natural smem layouts, online softmax.
// Grid: (SEQ/128, BH). Block 256 = 8 warps, warp w owns q rows [w*16, w*16+16).
// Smem (words): Qs [128][68] @0 (8704), Ks [64][68] @8704 (4352),
//               Vs [64][76] @13056 (4864), Ps 8x[16][68] @17920 (8704)
// total 26624 words = 106496 bytes.
// ---------------------------------------------------------------------------
#define FA_SMEM_BYTES 106496

__global__ __launch_bounds__(256, 2)
void flash_attn(const float* __restrict__ qk, const float* __restrict__ vbuf,
                float* __restrict__ out)
{
    extern __shared__ uint32_t sm[];
    uint32_t* Qs = sm;
    uint32_t* Ks = sm + 8704;
    uint32_t* Vs = sm + 13056;
    uint32_t* Ps = sm + 17920;
    const uint32_t sbase = (uint32_t)__cvta_generic_to_shared(sm);

    const int bh = blockIdx.y;
    const int b  = bh / HEADS, h = bh % HEADS;
    const int q0 = blockIdx.x * 128;
    const int tid  = threadIdx.x;
    const int w    = tid >> 5;
    const int lane = tid & 31;
    const int g    = lane >> 2;
    const int tq   = lane & 3;
    uint32_t* Pw = Ps + w * (16 * 68);

    const float* Qg = qk + (long)b * SEQ * QKDIM + h * HDIM;
    const float* Kg = Qg + EMBED;
    const float* Vg = vbuf + (long)b * SEQ * EMBED + h * HDIM;

    // K/V loader geometry: 64 rows x 64 cols, 16 floats per thread
    const int kr = tid & 63;
    const int kq = (tid >> 6) * 16;
    const uint32_t kdst = sbase + (8704  + kr * 68 + kq) * 4;
    const uint32_t vdst = sbase + (13056 + kr * 76 + kq) * 4;

    // ---- load Q tile (128 x 64), scale 1/8, natural [m][k] stride 68 ----
    {
        const int qr = tid & 127;
        const int qc = (tid >> 7) * 32;
        const float* src = Qg + (long)(q0 + qr) * QKDIM + qc;
        #pragma unroll
        for (int i = 0; i < 32; i += 4) {
            float4 v = *(const float4*)(src + i);
            v.x *= 0.125f; v.y *= 0.125f; v.z *= 0.125f; v.w *= 0.125f;
            *(uint4*)&Qs[qr * 68 + qc + i] = f4bits(v);
        }
    }

    float oacc[8][4];
    #pragma unroll
    for (int j = 0; j < 8; j++)
        #pragma unroll
        for (int r = 0; r < 4; r++) oacc[j][r] = 0.0f;
    float mrow0 = -INFINITY, mrow1 = -INFINITY;
    float lrow0 = 0.0f, lrow1 = 0.0f;

    for (int kv = 0; kv < SEQ; kv += 64) {
        __syncthreads();   // prior reads of Ks/Vs complete (covers Q on iter 0)

        // ---- async K + V tile loads ----
        {
            const float* ks = Kg + (long)(kv + kr) * QKDIM + kq;
            const float* vs = Vg + (long)(kv + kr) * EMBED + kq;
            #pragma unroll
            for (int i = 0; i < 4; i++) cp16(kdst + i * 16, ks + i * 4);
            #pragma unroll
            for (int i = 0; i < 4; i++) cp16(vdst + i * 16, vs + i * 4);
        }
        cp_commit();
        cp_wait0();
        __syncthreads();   // Ks, Vs ready for all warps

        // ---- S = (Q/8) @ K^T ----
        float sacc[8][4];
        #pragma unroll
        for (int j = 0; j < 8; j++)
            #pragma unroll
            for (int r = 0; r < 4; r++) sacc[j][r] = 0.0f;

        const int mb = w * 16;
        #pragma unroll
        for (int kk = 0; kk < 64; kk += 8) {
            uint32_t af[4];
            const uint32_t* qp = Qs + (mb + g) * 68 + kk + tq;
            af[0] = qp[0];
            af[1] = qp[8 * 68];
            af[2] = qp[4];
            af[3] = qp[8 * 68 + 4];
            #pragma unroll
            for (int j = 0; j < 8; j++) {
                uint32_t bf[2];
                bf[0] = Ks[(j * 8 + g) * 68 + kk + tq    ];
                bf[1] = Ks[(j * 8 + g) * 68 + kk + tq + 4];
                mma_tf32(sacc[j], af, bf);
            }
        }

        // ---- online softmax (rows g and g+8 of warp tile) ----
        float tmax0 = -INFINITY, tmax1 = -INFINITY;
        #pragma unroll
        for (int j = 0; j < 8; j++) {
            tmax0 = fmaxf(tmax0, fmaxf(sacc[j][0], sacc[j][1]));
            tmax1 = fmaxf(tmax1, fmaxf(sacc[j][2], sacc[j][3]));
        }
        #pragma unroll
        for (int o = 1; o < 4; o <<= 1) {
            tmax0 = fmaxf(tmax0, __shfl_xor_sync(0xFFFFFFFFu, tmax0, o));
            tmax1 = fmaxf(tmax1, __shfl_xor_sync(0xFFFFFFFFu, tmax1, o));
        }
        const float mnew0 = fmaxf(mrow0, tmax0);
        const float mnew1 = fmaxf(mrow1, tmax1);
        const float alpha0 = __expf(mrow0 - mnew0);
        const float alpha1 = __expf(mrow1 - mnew1);
        mrow0 = mnew0; mrow1 = mnew1;

        float sum0 = 0.0f, sum1 = 0.0f;
        #pragma unroll
        for (int j = 0; j < 8; j++) {
            sacc[j][0] = __expf(sacc[j][0] - mnew0);
            sacc[j][1] = __expf(sacc[j][1] - mnew0);
            sacc[j][2] = __expf(sacc[j][2] - mnew1);
            sacc[j][3] = __expf(sacc[j][3] - mnew1);
            sum0 += sacc[j][0] + sacc[j][1];
            sum1 += sacc[j][2] + sacc[j][3];
        }
        #pragma unroll
        for (int o = 1; o < 4; o <<= 1) {
            sum0 += __shfl_xor_sync(0xFFFFFFFFu, sum0, o);
            sum1 += __shfl_xor_sync(0xFFFFFFFFu, sum1, o);
        }
        lrow0 = lrow0 * alpha0 + sum0;
        lrow1 = lrow1 * alpha1 + sum1;

        #pragma unroll
        for (int j = 0; j < 8; j++) {
            oacc[j][0] *= alpha0; oacc[j][1] *= alpha0;
            oacc[j][2] *= alpha1; oacc[j][3] *= alpha1;
        }

        // ---- stage P (raw bits, warp-private) ----
        #pragma unroll
        for (int j = 0; j < 8; j++) {
            Pw[ g      * 68 + j * 8 + tq * 2    ] = __float_as_uint(sacc[j][0]);
            Pw[ g      * 68 + j * 8 + tq * 2 + 1] = __float_as_uint(sacc[j][1]);
            Pw[(g + 8) * 68 + j * 8 + tq * 2    ] = __float_as_uint(sacc[j][2]);
            Pw[(g + 8) * 68 + j * 8 + tq * 2 + 1] = __float_as_uint(sacc[j][3]);
        }
        __syncwarp();

        // ---- O += P @ V ----
        #pragma unroll
        for (int kk = 0; kk < 64; kk += 8) {
            uint32_t af[4];
            af[0] = Pw[ g      * 68 + kk + tq    ];
            af[1] = Pw[(g + 8) * 68 + kk + tq    ];
            af[2] = Pw[ g      * 68 + kk + tq + 4];
            af[3] = Pw[(g + 8) * 68 + kk + tq + 4];
            #pragma unroll
            for (int j = 0; j < 8; j++) {
                uint32_t bf[2];
                bf[0] = Vs[(kk + tq    ) * 76 + j * 8 + g];
                bf[1] = Vs[(kk + tq + 4) * 76 + j * 8 + g];
                mma_tf32(oacc[j], af, bf);
            }
        }
        __syncwarp();
    }

    // ---- epilogue ----
    const float inv0 = 1.0f / lrow0;
    const float inv1 = 1.0f / lrow1;
    const long row0 = (long)(b * SEQ + q0 + w * 16 + g);
    #pragma unroll
    for (int j = 0; j < 8; j++) {
        const int col = h * HDIM + j * 8 + tq * 2;
        float2 o0; o0.x = oacc[j][0] * inv0; o0.y = oacc[j][1] * inv0;
        float2 o1; o1.x = oacc[j][2] * inv1; o1.y = oacc[j][3] * inv1;
        *(float2*)(out + row0 * EMBED + col)       = o0;
        *(float2*)(out + (row0 + 8) * EMBED + col) = o1;
    }
}

// ---------------------------------------------------------------------------
// Launch
// ---------------------------------------------------------------------------
extern "C" void kernel_launch(void* const* d_in, const int* in_sizes, int n_in,
                              void* d_out, int out_size)
{
    const float* x      = (const float*)d_in[0];
    const float* ln1_g  = (const float*)d_in[1];
    const float* ln1_b  = (const float*)d_in[2];
    const float* qk_w   = (const float*)d_in[3];
    const float* v_w    = (const float*)d_in[4];
    const float* proj_w = (const float*)d_in[5];
    const float* proj_b = (const float*)d_in[6];
    const float* ln2_g  = (const float*)d_in[7];
    const float* ln2_b  = (const float*)d_in[8];
    const float* fc1_w  = (const float*)d_in[9];
    const float* fc1_b  = (const float*)d_in[10];
    const float* fc2_w  = (const float*)d_in[11];
    const float* fc2_b  = (const float*)d_in[12];
    float* out = (float*)d_out;

    float *h1, *qkb, *vb, *att, *x2, *h2, *m1;
    cudaGetSymbolAddress((void**)&h1,  g_h1);
    cudaGetSymbolAddress((void**)&qkb, g_qk);
    cudaGetSymbolAddress((void**)&vb,  g_v);
    cudaGetSymbolAddress((void**)&att, g_att);
    cudaGetSymbolAddress((void**)&x2,  g_x2);
    cudaGetSymbolAddress((void**)&h2,  g_h2);
    cudaGetSymbolAddress((void**)&m1,  g_m1);

    static bool attr_done = false;
    if (!attr_done) {
        cudaFuncSetAttribute(flash_attn,
                             cudaFuncAttributeMaxDynamicSharedMemorySize,
                             FA_SMEM_BYTES);
        cudaFuncSetAttribute(gemm_tf32<EPI_NONE>,
                             cudaFuncAttributeMaxDynamicSharedMemorySize,
                             GEMM_SMEM_BYTES);
        cudaFuncSetAttribute(gemm_tf32<EPI_GELU>,
                             cudaFuncAttributeMaxDynamicSharedMemorySize,
                             GEMM_SMEM_BYTES);
        cudaFuncSetAttribute(gemm_tf32<EPI_BIASRES>,
                             cudaFuncAttributeMaxDynamicSharedMemorySize,
                             GEMM_SMEM_BYTES);
        attr_done = true;
    }

    // --- attention branch ---
    ln_kernel<<<ROWS, 256>>>(x, ln1_g, ln1_b, h1);

    gemm_tf32<EPI_NONE><<<dim3(QKDIM / 128, ROWS / 128), 256, GEMM_SMEM_BYTES>>>(
        h1, qk_w, nullptr, nullptr, qkb, ROWS, QKDIM, EMBED);
    gemm_tf32<EPI_NONE><<<dim3(EMBED / 128, ROWS / 128), 256, GEMM_SMEM_BYTES>>>(
        h1, v_w, nullptr, nullptr, vb, ROWS, EMBED, EMBED);

    flash_attn<<<dim3(SEQ / 128, BH), 256, FA_SMEM_BYTES>>>(qkb, vb, att);

    gemm_tf32<EPI_BIASRES><<<dim3(EMBED / 128, ROWS / 128), 256, GEMM_SMEM_BYTES>>>(
        att, proj_w, proj_b, x, x2, ROWS, EMBED, EMBED);

    // --- MLP branch ---
    ln_kernel<<<ROWS, 256>>>(x2, ln2_g, ln2_b, h2);

    gemm_tf32<EPI_GELU><<<dim3(MLPDIM / 128, ROWS / 128), 256, GEMM_SMEM_BYTES>>>(
        h2, fc1_w, fc1_b, nullptr, m1, ROWS, MLPDIM, EMBED);

    gemm_tf32<EPI_BIASRES><<<dim3(EMBED / 128, ROWS / 128), 256, GEMM_SMEM_BYTES>>>(
        m1, fc2_w, fc2_b, x2, out, ROWS, EMBED, MLPDIM);
}

// round 7
// speedup vs baseline: 1.1257x; 1.0888x over previous
#include <cuda_runtime.h>
#include <cuda_bf16.h>
#include <math.h>
#include <stdint.h>

// ---------------------------------------------------------------------------
// Problem constants
// ---------------------------------------------------------------------------
#define BATCH   8
#define SEQ     1024
#define ROWS    (BATCH * SEQ)        // 8192
#define EMBED   768
#define HEADS   12
#define HDIM    64
#define QKDIM   (2 * EMBED)          // 1536
#define MLPDIM  3072
#define BH      (BATCH * HEADS)      // 96

// ---------------------------------------------------------------------------
// Device scratch (static globals — allocation-free)
// ---------------------------------------------------------------------------
__device__ float g_h1[(size_t)ROWS * EMBED];
__device__ float g_qk[(size_t)ROWS * QKDIM];
__device__ float g_v [(size_t)ROWS * EMBED];
__device__ float g_att[(size_t)ROWS * EMBED];
__device__ float g_x2[(size_t)ROWS * EMBED];
__device__ float g_h2[(size_t)ROWS * EMBED];
__device__ float g_m1[(size_t)ROWS * MLPDIM];

// ---------------------------------------------------------------------------
// Helpers
// ---------------------------------------------------------------------------
__device__ __forceinline__ void mma_tf32(float c[4],
                                         const uint32_t a[4],
                                         const uint32_t b[2]) {
    asm volatile(
        "mma.sync.aligned.m16n8k8.row.col.f32.tf32.tf32.f32 "
        "{%0,%1,%2,%3}, {%4,%5,%6,%7}, {%8,%9}, {%0,%1,%2,%3};"
        : "+f"(c[0]), "+f"(c[1]), "+f"(c[2]), "+f"(c[3])
        : "r"(a[0]), "r"(a[1]), "r"(a[2]), "r"(a[3]),
          "r"(b[0]), "r"(b[1]));
}

__device__ __forceinline__ void cp16(uint32_t dst, const void* src) {
    asm volatile("cp.async.cg.shared.global [%0], [%1], 16;" :: "r"(dst), "l"(src));
}
__device__ __forceinline__ void cp_commit() {
    asm volatile("cp.async.commit_group;");
}
__device__ __forceinline__ void cp_wait0() {
    asm volatile("cp.async.wait_group 0;");
}

__device__ __forceinline__ uint4 f4bits(float4 v) {
    uint4 u;
    u.x = __float_as_uint(v.x); u.y = __float_as_uint(v.y);
    u.z = __float_as_uint(v.z); u.w = __float_as_uint(v.w);
    return u;
}

// ---------------------------------------------------------------------------
// LayerNorm: one block per row
// ---------------------------------------------------------------------------
__global__ __launch_bounds__(256)
void ln_kernel(const float* __restrict__ x, const float* __restrict__ g,
               const float* __restrict__ b, float* __restrict__ out)
{
    __shared__ float s1[8], s2[8];
    const long row = blockIdx.x;
    const float* p = x + row * EMBED;
    const int tid = threadIdx.x;

    float v0 = p[tid], v1 = p[tid + 256], v2 = p[tid + 512];
    float s = v0 + v1 + v2;
    float q = v0 * v0 + v1 * v1 + v2 * v2;
    #pragma unroll
    for (int o = 16; o; o >>= 1) {
        s += __shfl_xor_sync(0xFFFFFFFFu, s, o);
        q += __shfl_xor_sync(0xFFFFFFFFu, q, o);
    }
    if ((tid & 31) == 0) { s1[tid >> 5] = s; s2[tid >> 5] = q; }
    __syncthreads();
    if (tid < 32) {
        s = (tid < 8) ? s1[tid] : 0.0f;
        q = (tid < 8) ? s2[tid] : 0.0f;
        #pragma unroll
        for (int o = 4; o; o >>= 1) {
            s += __shfl_xor_sync(0xFFFFFFFFu, s, o);
            q += __shfl_xor_sync(0xFFFFFFFFu, q, o);
        }
        if (tid == 0) { s1[0] = s; s2[0] = q; }
    }
    __syncthreads();
    const float inv = 1.0f / (float)EMBED;
    const float mu  = s1[0] * inv;
    const float var = s2[0] * inv - mu * mu;
    const float rstd = rsqrtf(var + 1e-5f);
    float* po = out + row * EMBED;
    po[tid      ] = (v0 - mu) * rstd * g[tid      ] + b[tid      ];
    po[tid + 256] = (v1 - mu) * rstd * g[tid + 256] + b[tid + 256];
    po[tid + 512] = (v2 - mu) * rstd * g[tid + 512] + b[tid + 512];
}

// ---------------------------------------------------------------------------
// TF32 GEMM v4: register-prefetch double-buffered, raw fp32 operands.
// 128x128 block tile, BK=16, 256 threads (8 warps, 2x4), warp tile 64x32.
// A smem: [2][128][20]  natural [m][k] (stride 20 => conflict-free frags)
// B smem: [2][16][136]  [k][n]         (stride 136 => conflict-free frags)
// Total smem 37888 B; __launch_bounds__(256,2) => 2 CTAs/SM.
// ---------------------------------------------------------------------------
#define EPI_NONE     0
#define EPI_GELU     2
#define EPI_BIASRES  3

template<int EPI>
__global__ __launch_bounds__(256, 2)
void gemm_tf32(const float* __restrict__ A, const float* __restrict__ B,
               const float* __restrict__ bias, const float* __restrict__ res,
               float* __restrict__ C, int M, int N, int K)
{
    __shared__ uint32_t As[2][128 * 20];
    __shared__ uint32_t Bs[2][16 * 136];

    const int tid  = threadIdx.x;
    const int bm   = blockIdx.y * 128;
    const int bn   = blockIdx.x * 128;
    const int w    = tid >> 5;
    const int lane = tid & 31;
    const int m0   = (w >> 2) * 64;
    const int n0   = (w & 3) * 32;
    const int g    = lane >> 2;
    const int tq   = lane & 3;

    // loader geometry
    const int ar = tid >> 1;           // A row 0..127
    const int ac = (tid & 1) * 8;      // A k base (0 or 8)
    const int br = tid >> 4;           // B k-row 0..15
    const int bc = (tid & 15) * 4;     // B col base 0..60 (plus +64 chunk)

    const float* Ag = A + (long)(bm + ar) * K + ac;
    const float* Bg = B + (long)br * N + bn + bc;

    float acc[4][4][4];
    #pragma unroll
    for (int i = 0; i < 4; i++)
        #pragma unroll
        for (int j = 0; j < 4; j++)
            #pragma unroll
            for (int r = 0; r < 4; r++) acc[i][j][r] = 0.0f;

    // load tile 0 -> regs -> stage 0
    float4 apf0 = *(const float4*)(Ag);
    float4 apf1 = *(const float4*)(Ag + 4);
    float4 bpf0 = *(const float4*)(Bg);
    float4 bpf1 = *(const float4*)(Bg + 64);
    *(uint4*)&As[0][ar * 20 + ac]        = f4bits(apf0);
    *(uint4*)&As[0][ar * 20 + ac + 4]    = f4bits(apf1);
    *(uint4*)&Bs[0][br * 136 + bc]       = f4bits(bpf0);
    *(uint4*)&Bs[0][br * 136 + bc + 64]  = f4bits(bpf1);
    __syncthreads();

    const int NT = K >> 4;
    for (int t = 0; t < NT; t++) {
        // ---- prefetch tile t+1 into registers (latency hidden by compute) ----
        const bool more = (t + 1 < NT);
        if (more) {
            const float* ap = Ag + (t + 1) * 16;
            const float* bp = Bg + (long)(t + 1) * 16 * N;
            apf0 = *(const float4*)(ap);
            apf1 = *(const float4*)(ap + 4);
            bpf0 = *(const float4*)(bp);
            bpf1 = *(const float4*)(bp + 64);
        }

        // ---- compute stage t&1 ----
        const uint32_t* Asb = As[t & 1];
        const uint32_t* Bsb = Bs[t & 1];
        #pragma unroll
        for (int kk = 0; kk < 16; kk += 8) {
            uint32_t af[4][4];
            uint32_t bf[4][2];
            #pragma unroll
            for (int i = 0; i < 4; i++) {
                const uint32_t* ap = Asb + (m0 + i * 16 + g) * 20 + kk + tq;
                af[i][0] = ap[0];
                af[i][1] = ap[8 * 20];
                af[i][2] = ap[4];
                af[i][3] = ap[8 * 20 + 4];
            }
            #pragma unroll
            for (int j = 0; j < 4; j++) {
                bf[j][0] = Bsb[(kk + tq    ) * 136 + n0 + j * 8 + g];
                bf[j][1] = Bsb[(kk + tq + 4) * 136 + n0 + j * 8 + g];
            }
            #pragma unroll
            for (int i = 0; i < 4; i++)
                #pragma unroll
                for (int j = 0; j < 4; j++)
                    mma_tf32(acc[i][j], af[i], bf[j]);
        }

        // ---- store prefetch into the other stage ----
        if (more) {
            const int s = (t + 1) & 1;
            *(uint4*)&As[s][ar * 20 + ac]       = f4bits(apf0);
            *(uint4*)&As[s][ar * 20 + ac + 4]   = f4bits(apf1);
            *(uint4*)&Bs[s][br * 136 + bc]      = f4bits(bpf0);
            *(uint4*)&Bs[s][br * 136 + bc + 64] = f4bits(bpf1);
            __syncthreads();
        }
    }

    // epilogue
    #pragma unroll
    for (int i = 0; i < 4; i++) {
        const int row0 = bm + m0 + i * 16 + g;
        #pragma unroll
        for (int j = 0; j < 4; j++) {
            const int col = bn + n0 + j * 8 + tq * 2;
            float b0 = 0.0f, b1 = 0.0f;
            if (EPI != EPI_NONE) { b0 = bias[col]; b1 = bias[col + 1]; }
            #pragma unroll
            for (int half = 0; half < 2; half++) {
                const long base = (long)(row0 + half * 8) * N + col;
                float c0 = acc[i][j][half * 2 + 0];
                float c1 = acc[i][j][half * 2 + 1];
                if (EPI != EPI_NONE) { c0 += b0; c1 += b1; }
                if (EPI == EPI_GELU) {
                    c0 = 0.5f * c0 * (1.0f + erff(c0 * 0.70710678118654752f));
                    c1 = 0.5f * c1 * (1.0f + erff(c1 * 0.70710678118654752f));
                }
                if (EPI == EPI_BIASRES) { c0 += res[base]; c1 += res[base + 1]; }
                float2 o; o.x = c0; o.y = c1;
                *(float2*)(C + base) = o;
            }
        }
    }
}

// ---------------------------------------------------------------------------
// Fused flash attention (R5 version — 361 us, validated)
// ---------------------------------------------------------------------------
#define FA_SMEM_BYTES 106496

__global__ __launch_bounds__(256, 2)
void flash_attn(const float* __restrict__ qk, const float* __restrict__ vbuf,
                float* __restrict__ out)
{
    extern __shared__ uint32_t sm[];
    uint32_t* Qs = sm;
    uint32_t* Ks = sm + 8704;
    uint32_t* Vs = sm + 13056;
    uint32_t* Ps = sm + 17920;
    const uint32_t sbase = (uint32_t)__cvta_generic_to_shared(sm);

    const int bh = blockIdx.y;
    const int b  = bh / HEADS, h = bh % HEADS;
    const int q0 = blockIdx.x * 128;
    const int tid  = threadIdx.x;
    const int w    = tid >> 5;
    const int lane = tid & 31;
    const int g    = lane >> 2;
    const int tq   = lane & 3;
    uint32_t* Pw = Ps + w * (16 * 68);

    const float* Qg = qk + (long)b * SEQ * QKDIM + h * HDIM;
    const float* Kg = Qg + EMBED;
    const float* Vg = vbuf + (long)b * SEQ * EMBED + h * HDIM;

    const int kr = tid & 63;
    const int kq = (tid >> 6) * 16;
    const uint32_t kdst = sbase + (8704  + kr * 68 + kq) * 4;
    const uint32_t vdst = sbase + (13056 + kr * 76 + kq) * 4;

    {
        const int qr = tid & 127;
        const int qc = (tid >> 7) * 32;
        const float* src = Qg + (long)(q0 + qr) * QKDIM + qc;
        #pragma unroll
        for (int i = 0; i < 32; i += 4) {
            float4 v = *(const float4*)(src + i);
            v.x *= 0.125f; v.y *= 0.125f; v.z *= 0.125f; v.w *= 0.125f;
            *(uint4*)&Qs[qr * 68 + qc + i] = f4bits(v);
        }
    }

    float oacc[8][4];
    #pragma unroll
    for (int j = 0; j < 8; j++)
        #pragma unroll
        for (int r = 0; r < 4; r++) oacc[j][r] = 0.0f;
    float mrow0 = -INFINITY, mrow1 = -INFINITY;
    float lrow0 = 0.0f, lrow1 = 0.0f;

    for (int kv = 0; kv < SEQ; kv += 64) {
        __syncthreads();
        {
            const float* ks = Kg + (long)(kv + kr) * QKDIM + kq;
            const float* vs = Vg + (long)(kv + kr) * EMBED + kq;
            #pragma unroll
            for (int i = 0; i < 4; i++) cp16(kdst + i * 16, ks + i * 4);
            #pragma unroll
            for (int i = 0; i < 4; i++) cp16(vdst + i * 16, vs + i * 4);
        }
        cp_commit();
        cp_wait0();
        __syncthreads();

        float sacc[8][4];
        #pragma unroll
        for (int j = 0; j < 8; j++)
            #pragma unroll
            for (int r = 0; r < 4; r++) sacc[j][r] = 0.0f;

        const int mb = w * 16;
        #pragma unroll
        for (int kk = 0; kk < 64; kk += 8) {
            uint32_t af[4];
            const uint32_t* qp = Qs + (mb + g) * 68 + kk + tq;
            af[0] = qp[0];
            af[1] = qp[8 * 68];
            af[2] = qp[4];
            af[3] = qp[8 * 68 + 4];
            #pragma unroll
            for (int j = 0; j < 8; j++) {
                uint32_t bf[2];
                bf[0] = Ks[(j * 8 + g) * 68 + kk + tq    ];
                bf[1] = Ks[(j * 8 + g) * 68 + kk + tq + 4];
                mma_tf32(sacc[j], af, bf);
            }
        }

        float tmax0 = -INFINITY, tmax1 = -INFINITY;
        #pragma unroll
        for (int j = 0; j < 8; j++) {
            tmax0 = fmaxf(tmax0, fmaxf(sacc[j][0], sacc[j][1]));
            tmax1 = fmaxf(tmax1, fmaxf(sacc[j][2], sacc[j][3]));
        }
        #pragma unroll
        for (int o = 1; o < 4; o <<= 1) {
            tmax0 = fmaxf(tmax0, __shfl_xor_sync(0xFFFFFFFFu, tmax0, o));
            tmax1 = fmaxf(tmax1, __shfl_xor_sync(0xFFFFFFFFu, tmax1, o));
        }
        const float mnew0 = fmaxf(mrow0, tmax0);
        const float mnew1 = fmaxf(mrow1, tmax1);
        const float alpha0 = __expf(mrow0 - mnew0);
        const float alpha1 = __expf(mrow1 - mnew1);
        mrow0 = mnew0; mrow1 = mnew1;

        float sum0 = 0.0f, sum1 = 0.0f;
        #pragma unroll
        for (int j = 0; j < 8; j++) {
            sacc[j][0] = __expf(sacc[j][0] - mnew0);
            sacc[j][1] = __expf(sacc[j][1] - mnew0);
            sacc[j][2] = __expf(sacc[j][2] - mnew1);
            sacc[j][3] = __expf(sacc[j][3] - mnew1);
            sum0 += sacc[j][0] + sacc[j][1];
            sum1 += sacc[j][2] + sacc[j][3];
        }
        #pragma unroll
        for (int o = 1; o < 4; o <<= 1) {
            sum0 += __shfl_xor_sync(0xFFFFFFFFu, sum0, o);
            sum1 += __shfl_xor_sync(0xFFFFFFFFu, sum1, o);
        }
        lrow0 = lrow0 * alpha0 + sum0;
        lrow1 = lrow1 * alpha1 + sum1;

        #pragma unroll
        for (int j = 0; j < 8; j++) {
            oacc[j][0] *= alpha0; oacc[j][1] *= alpha0;
            oacc[j][2] *= alpha1; oacc[j][3] *= alpha1;
        }

        #pragma unroll
        for (int j = 0; j < 8; j++) {
            Pw[ g      * 68 + j * 8 + tq * 2    ] = __float_as_uint(sacc[j][0]);
            Pw[ g      * 68 + j * 8 + tq * 2 + 1] = __float_as_uint(sacc[j][1]);
            Pw[(g + 8) * 68 + j * 8 + tq * 2    ] = __float_as_uint(sacc[j][2]);
            Pw[(g + 8) * 68 + j * 8 + tq * 2 + 1] = __float_as_uint(sacc[j][3]);
        }
        __syncwarp();

        #pragma unroll
        for (int kk = 0; kk < 64; kk += 8) {
            uint32_t af[4];
            af[0] = Pw[ g      * 68 + kk + tq    ];
            af[1] = Pw[(g + 8) * 68 + kk + tq    ];
            af[2] = Pw[ g      * 68 + kk + tq + 4];
            af[3] = Pw[(g + 8) * 68 + kk + tq + 4];
            #pragma unroll
            for (int j = 0; j < 8; j++) {
                uint32_t bf[2];
                bf[0] = Vs[(kk + tq    ) * 76 + j * 8 + g];
                bf[1] = Vs[(kk + tq + 4) * 76 + j * 8 + g];
                mma_tf32(oacc[j], af, bf);
            }
        }
        __syncwarp();
    }

    const float inv0 = 1.0f / lrow0;
    const float inv1 = 1.0f / lrow1;
    const long row0 = (long)(b * SEQ + q0 + w * 16 + g);
    #pragma unroll
    for (int j = 0; j < 8; j++) {
        const int col = h * HDIM + j * 8 + tq * 2;
        float2 o0; o0.x = oacc[j][0] * inv0; o0.y = oacc[j][1] * inv0;
        float2 o1; o1.x = oacc[j][2] * inv1; o1.y = oacc[j][3] * inv1;
        *(float2*)(out + row0 * EMBED + col)       = o0;
        *(float2*)(out + (row0 + 8) * EMBED + col) = o1;
    }
}

// ---------------------------------------------------------------------------
// Launch
// ---------------------------------------------------------------------------
extern "C" void kernel_launch(void* const* d_in, const int* in_sizes, int n_in,
                              void* d_out, int out_size)
{
    const float* x      = (const float*)d_in[0];
    const float* ln1_g  = (const float*)d_in[1];
    const float* ln1_b  = (const float*)d_in[2];
    const float* qk_w   = (const float*)d_in[3];
    const float* v_w    = (const float*)d_in[4];
    const float* proj_w = (const float*)d_in[5];
    const float* proj_b = (const float*)d_in[6];
    const float* ln2_g  = (const float*)d_in[7];
    const float* ln2_b  = (const float*)d_in[8];
    const float* fc1_w  = (const float*)d_in[9];
    const float* fc1_b  = (const float*)d_in[10];
    const float* fc2_w  = (const float*)d_in[11];
    const float* fc2_b  = (const float*)d_in[12];
    float* out = (float*)d_out;

    float *h1, *qkb, *vb, *att, *x2, *h2, *m1;
    cudaGetSymbolAddress((void**)&h1,  g_h1);
    cudaGetSymbolAddress((void**)&qkb, g_qk);
    cudaGetSymbolAddress((void**)&vb,  g_v);
    cudaGetSymbolAddress((void**)&att, g_att);
    cudaGetSymbolAddress((void**)&x2,  g_x2);
    cudaGetSymbolAddress((void**)&h2,  g_h2);
    cudaGetSymbolAddress((void**)&m1,  g_m1);

    static bool attr_done = false;
    if (!attr_done) {
        cudaFuncSetAttribute(flash_attn,
                             cudaFuncAttributeMaxDynamicSharedMemorySize,
                             FA_SMEM_BYTES);
        attr_done = true;
    }

    // --- attention branch ---
    ln_kernel<<<ROWS, 256>>>(x, ln1_g, ln1_b, h1);

    gemm_tf32<EPI_NONE><<<dim3(QKDIM / 128, ROWS / 128), 256>>>(
        h1, qk_w, nullptr, nullptr, qkb, ROWS, QKDIM, EMBED);
    gemm_tf32<EPI_NONE><<<dim3(EMBED / 128, ROWS / 128), 256>>>(
        h1, v_w, nullptr, nullptr, vb, ROWS, EMBED, EMBED);

    flash_attn<<<dim3(SEQ / 128, BH), 256, FA_SMEM_BYTES>>>(qkb, vb, att);

    gemm_tf32<EPI_BIASRES><<<dim3(EMBED / 128, ROWS / 128), 256>>>(
        att, proj_w, proj_b, x, x2, ROWS, EMBED, EMBED);

    // --- MLP branch ---
    ln_kernel<<<ROWS, 256>>>(x2, ln2_g, ln2_b, h2);

    gemm_tf32<EPI_GELU><<<dim3(MLPDIM / 128, ROWS / 128), 256>>>(
        h2, fc1_w, fc1_b, nullptr, m1, ROWS, MLPDIM, EMBED);

    gemm_tf32<EPI_BIASRES><<<dim3(EMBED / 128, ROWS / 128), 256>>>(
        m1, fc2_w, fc2_b, x2, out, ROWS, EMBED, MLPDIM);
}